// round 9
// baseline (speedup 1.0000x reference)
#include <cuda_runtime.h>
#include <cstdint>

// CRPS via cp.async.bulk (TMA path): per block, 1 thread issues 16 x 2KB
// bulk copies (one per sample row) into SMEM + mbarrier expect_tx. Loads
// are decoupled from registers -> full streaming BW. Compute: sort-identity
// term2 (Batcher-16, FMNMX/ALU pipe) reading conflict-free from SMEM.

#define NS   16
#define P    262144
#define NT   256
#define PX   2
#define TW   (NT * PX)          // tile width = 512 pixels
#define NB   (P / TW)           // 512 blocks
#define TILE_BYTES (NS * TW * 4)  // 32768
 
__device__ float        g_partial[NB];
__device__ unsigned int g_count = 0;

__device__ __forceinline__ uint32_t smem_u32(const void* p) {
    uint32_t a;
    asm("{ .reg .u64 t; cvta.to.shared.u64 t, %1; cvt.u32.u64 %0, t; }"
        : "=r"(a) : "l"(p));
    return a;
}

__device__ __forceinline__ void cas(float& a, float& b) {
    float lo = fminf(a, b);
    float hi = fmaxf(a, b);
    a = lo; b = hi;
}

__device__ __forceinline__ float crps_px(float v[NS], float t) {
    float a1 = 0.f;
#pragma unroll
    for (int i = 0; i < NS; i++) a1 += fabsf(v[i] - t);

    // Batcher odd-even mergesort, n=16 (63 CAS)
#pragma unroll
    for (int pp = 1; pp < NS; pp <<= 1) {
#pragma unroll
        for (int k = pp; k >= 1; k >>= 1) {
#pragma unroll
            for (int j = k % pp; j + k < NS; j += 2 * k) {
#pragma unroll
                for (int i = 0; i < k && i + j + k < NS; i++) {
                    if ((i + j) / (2 * pp) == (i + j + k) / (2 * pp))
                        cas(v[i + j], v[i + j + k]);
                }
            }
        }
    }

    float a2 = 0.f;
#pragma unroll
    for (int k = 0; k < NS; k++)
        a2 = fmaf((float)(2 * k - 15), v[k], a2);

    return a1 * (1.0f / 16.0f) - a2 * (1.0f / 256.0f);
}

__global__ void __launch_bounds__(NT)
k_crps(const float* __restrict__ s, const float* __restrict__ y,
       float* __restrict__ out) {
    __shared__ __align__(128) float tile[NS][TW];
    __shared__ __align__(8)  uint64_t mbar;

    const uint32_t mb = smem_u32(&mbar);
    const int tid  = threadIdx.x;
    const int base = blockIdx.x * TW;

    if (tid == 0) {
        asm volatile("mbarrier.init.shared.b64 [%0], %1;"
                     :: "r"(mb), "r"(1u) : "memory");
    }
    __syncthreads();

    if (tid == 0) {
        asm volatile("mbarrier.arrive.expect_tx.shared.b64 _, [%0], %1;"
                     :: "r"(mb), "r"((uint32_t)TILE_BYTES) : "memory");
#pragma unroll
        for (int i = 0; i < NS; i++) {
            const float* src = s + (size_t)i * P + base;
            uint32_t dst = smem_u32(&tile[i][0]);
            asm volatile(
                "cp.async.bulk.shared::cta.global.mbarrier::complete_tx::bytes "
                "[%0], [%1], %2, [%3];"
                :: "r"(dst), "l"(src), "r"(TW * 4u), "r"(mb) : "memory");
        }
    }

    // Target via LDG, in flight while bulk copies stream.
    const float t0 = __ldg(&y[base + tid]);
    const float t1 = __ldg(&y[base + tid + NT]);

    // Wait for all 32KB (acquire orders the ld.shared below).
    {
        uint32_t done;
        asm volatile(
            "{\n\t.reg .pred p;\n\t"
            "mbarrier.try_wait.parity.acquire.cta.shared::cta.b64 p, [%1], %2;\n\t"
            "selp.b32 %0, 1, 0, p;\n\t}"
            : "=r"(done) : "r"(mb), "r"(0u) : "memory");
        if (!done) {
            asm volatile(
                "{\n\t.reg .pred P1;\n\t"
                "W_%=:\n\t"
                "mbarrier.try_wait.parity.acquire.cta.shared::cta.b64 P1, [%0], %1, 0x989680;\n\t"
                "@P1 bra.uni D_%=;\n\t"
                "bra.uni W_%=;\n\t"
                "D_%=:\n\t}"
                :: "r"(mb), "r"(0u) : "memory");
        }
    }

    float v[NS];
#pragma unroll
    for (int i = 0; i < NS; i++) v[i] = tile[i][tid];
    float val = crps_px(v, t0);
#pragma unroll
    for (int i = 0; i < NS; i++) v[i] = tile[i][tid + NT];
    val += crps_px(v, t1);

    // Block reduction
#pragma unroll
    for (int o = 16; o > 0; o >>= 1)
        val += __shfl_xor_sync(0xFFFFFFFFu, val, o);

    __shared__ float sm[NT / 32];
    const int lane = tid & 31;
    const int wid  = tid >> 5;
    if (lane == 0) sm[wid] = val;
    __syncthreads();

    if (wid == 0) {
        float w = (lane < NT / 32) ? sm[lane] : 0.f;
#pragma unroll
        for (int o = 4; o > 0; o >>= 1)
            w += __shfl_xor_sync(0xFFFFFFFFu, w, o);
        if (lane == 0) g_partial[blockIdx.x] = w;
    }

    // Last-block finalize (counter self-resets -> graph-replay deterministic)
    __shared__ bool isLast;
    if (tid == 0) {
        __threadfence();
        isLast = (atomicAdd(&g_count, 1u) == NB - 1);
    }
    __syncthreads();

    if (isLast) {
        __threadfence();
        double d = 0.0;
#pragma unroll
        for (int r = 0; r < NB / NT; r++)
            d += (double)g_partial[tid + r * NT];
#pragma unroll
        for (int o = 16; o > 0; o >>= 1)
            d += __shfl_xor_sync(0xFFFFFFFFu, d, o);

        __shared__ double sd[NT / 32];
        if (lane == 0) sd[wid] = d;
        __syncthreads();
        if (wid == 0) {
            double e = (lane < NT / 32) ? sd[lane] : 0.0;
#pragma unroll
            for (int o = 4; o > 0; o >>= 1)
                e += __shfl_xor_sync(0xFFFFFFFFu, e, o);
            if (lane == 0) {
                *out = (float)(e * (1.0 / (double)P));
                g_count = 0;
            }
        }
    }
}

extern "C" void kernel_launch(void* const* d_in, const int* in_sizes, int n_in,
                              void* d_out, int out_size) {
    const float* samples = (const float*)d_in[0];
    const float* target  = (const float*)d_in[1];
    k_crps<<<NB, NT>>>(samples, target, (float*)d_out);
}